// round 1
// baseline (speedup 1.0000x reference)
#include <cuda_runtime.h>
#include <cstdint>

// UpSmpl_3066606649708 — fused conv3d(64->256, 3x3x3, pad1) + pixel-shuffle x2
// + skip-add, direct-conv with packed f32x2 FMA (FFMA2) and cp.async pipeline.
//
// x:   (1, 64, 17, 128, 128) f32
// W:   (256, 64, 3, 3, 3)    f32
// b:   (256,)                f32
// out: (1, 32, 33, 256, 256) f32

#define ICN 64
#define ZD  17
#define NTHREADS 256
#define TYH 8          // y rows per block
#define TXW 32         // x cols per block
#define OCB 64         // output channels per block

#define XSLAB (3*10*34)   // 1020 floats: 3 z x 10 y x 34 x
#define WSLAB (27*64)     // 1728 floats: 27 taps x 64 oc

__device__ __forceinline__ unsigned long long pack2(float lo, float hi) {
    unsigned long long r;
    asm("mov.b64 %0, {%1,%2};" : "=l"(r) : "f"(lo), "f"(hi));
    return r;
}
__device__ __forceinline__ void unpack2(unsigned long long v, float& lo, float& hi) {
    asm("mov.b64 {%0,%1}, %2;" : "=f"(lo), "=f"(hi) : "l"(v));
}
__device__ __forceinline__ unsigned long long ffma2(unsigned long long a,
                                                    unsigned long long b,
                                                    unsigned long long c) {
    unsigned long long d;
    asm("fma.rn.f32x2 %0, %1, %2, %3;" : "=l"(d) : "l"(a), "l"(b), "l"(c));
    return d;
}
__device__ __forceinline__ void cpa4(uint32_t dst, const void* src, int bytes) {
    asm volatile("cp.async.ca.shared.global [%0], [%1], 4, %2;"
                 :: "r"(dst), "l"(src), "r"(bytes));
}

__global__ void __launch_bounds__(NTHREADS)
upsmpl_kernel(const float* __restrict__ xin, const float* __restrict__ win,
              const float* __restrict__ bin, float* __restrict__ outp)
{
    __shared__ __align__(16) float sx[2][XSLAB];
    __shared__ __align__(16) float sw[2][WSLAB];

    const int tid  = threadIdx.x;
    const int lane = tid & 31;
    const int og   = tid >> 5;              // 0..7: oc group (8 oc each)

    const int xt     = blockIdx.x;           // 0..3
    const int yt     = blockIdx.y;           // 0..15
    const int z      = blockIdx.z >> 2;      // 0..16
    const int oct    = blockIdx.z & 3;       // 0..3
    const int ocbase = oct * OCB;

    const int gx0 = xt * TXW;
    const int gy0 = yt * TYH;

    auto prefetch = [&](int ic, int s) {
        uint32_t sx_base = (uint32_t)__cvta_generic_to_shared(&sx[s][0]);
        uint32_t sw_base = (uint32_t)__cvta_generic_to_shared(&sw[s][0]);
        // x slab: z in {z-1,z,z+1}, y in [gy0-1, gy0+8], x in [gx0-1, gx0+32]
        for (int l = tid; l < XSLAB; l += NTHREADS) {
            int kz  = l / 340;
            int rem = l - kz * 340;
            int row = rem / 34;
            int col = rem - row * 34;
            int zs = z - 1 + kz;
            int ys = gy0 - 1 + row;
            int xs = gx0 - 1 + col;
            bool ok = ((unsigned)zs < 17u) & ((unsigned)ys < 128u) & ((unsigned)xs < 128u);
            long idx = ((long)(ic * 17 + (ok ? zs : 0)) * 128 + (ok ? ys : 0)) * 128
                       + (ok ? xs : 0);
            cpa4(sx_base + (uint32_t)l * 4u, xin + idx, ok ? 4 : 0);
        }
        // W slab: smem layout [tap][oc], oc contiguous (pairs feed FFMA2 via LDS.64)
        for (int l = tid; l < WSLAB; l += NTHREADS) {
            int oci = l / 27;
            int tap = l - oci * 27;
            const float* src = win + ((long)(ocbase + oci) * 64 + ic) * 27 + tap;
            cpa4(sw_base + (uint32_t)(tap * 64 + oci) * 4u, src, 4);
        }
    };

    unsigned long long acc[TYH][4];
    #pragma unroll
    for (int r = 0; r < TYH; ++r)
        #pragma unroll
        for (int j = 0; j < 4; ++j) acc[r][j] = 0ull;

    prefetch(0, 0);
    asm volatile("cp.async.commit_group;");

    for (int ic = 0; ic < ICN; ++ic) {
        const int cur = ic & 1;
        if (ic + 1 < ICN) {
            prefetch(ic + 1, cur ^ 1);
            asm volatile("cp.async.commit_group;");
            asm volatile("cp.async.wait_group 1;");
        } else {
            asm volatile("cp.async.wait_group 0;");
        }
        __syncthreads();

        const float* sxp = sx[cur];
        const float* swp = sw[cur];

        #pragma unroll
        for (int kz = 0; kz < 3; ++kz) {
            #pragma unroll
            for (int kx = 0; kx < 3; ++kx) {
                // cache 10 x values (rows 0..9) for this (kz, kx); reuse across ky
                unsigned long long xp[10];
                #pragma unroll
                for (int r = 0; r < 10; ++r) {
                    float v = sxp[kz * 340 + r * 34 + lane + kx];
                    xp[r] = pack2(v, v);
                }
                #pragma unroll
                for (int ky = 0; ky < 3; ++ky) {
                    const int tap = (kz * 3 + ky) * 3 + kx;
                    const unsigned long long* wq =
                        (const unsigned long long*)(swp + tap * 64 + og * 8);
                    unsigned long long w0 = wq[0], w1 = wq[1], w2 = wq[2], w3 = wq[3];
                    #pragma unroll
                    for (int r = 0; r < TYH; ++r) {
                        unsigned long long xv = xp[r + ky];
                        acc[r][0] = ffma2(xv, w0, acc[r][0]);
                        acc[r][1] = ffma2(xv, w1, acc[r][1]);
                        acc[r][2] = ffma2(xv, w2, acc[r][2]);
                        acc[r][3] = ffma2(xv, w3, acc[r][3]);
                    }
                }
            }
        }
        __syncthreads();
    }

    // Epilogue: bias + pixel-shuffle scatter + repeated-channel skip add.
    const int xg = gx0 + lane;
    #pragma unroll
    for (int r = 0; r < TYH; ++r) {
        const int yg = gy0 + r;
        #pragma unroll
        for (int j = 0; j < 4; ++j) {
            float v0, v1;
            unpack2(acc[r][j], v0, v1);
            #pragma unroll
            for (int h = 0; h < 2; ++h) {
                const float v = h ? v1 : v0;
                const int oc = ocbase + og * 8 + j * 2 + h;
                int n, p, q, F, sic;
                if (z == 0) {
                    // r1=1 shuffle on frame 0: oc = p*128 + q*64 + n64; keep n64<32
                    if (oc & 32) continue;
                    n = oc & 31;
                    q = (oc >> 6) & 1;
                    p = oc >> 7;
                    F = 0;
                    sic = (p * 64 + q * 32 + n) >> 1;   // repeat(x, 2) channel map
                } else {
                    // r1=2 shuffle on frames 1..16: oc = a*128 + p*64 + q*32 + n
                    n = oc & 31;
                    q = (oc >> 5) & 1;
                    p = (oc >> 6) & 1;
                    const int a = oc >> 7;
                    F = 2 * z - 1 + a;
                    sic = oc >> 2;                      // repeat(x, 4) channel map
                }
                const float skip = xin[((long)(sic * 17 + z) * 128 + yg) * 128 + xg];
                const float val  = v + bin[oc] + skip;
                const int Y = 2 * yg + p;
                const int X = 2 * xg + q;
                outp[((long)(n * 33 + F) * 256 + Y) * 256 + X] = val;
            }
        }
    }
}

extern "C" void kernel_launch(void* const* d_in, const int* in_sizes, int n_in,
                              void* d_out, int out_size) {
    const float* x = (const float*)d_in[0];
    const float* W = (const float*)d_in[1];
    const float* b = (const float*)d_in[2];
    float* out = (float*)d_out;
    dim3 grid(4, 16, 17 * 4);   // x-tiles, y-tiles, z * oc-tiles
    upsmpl_kernel<<<grid, NTHREADS>>>(x, W, b, out);
}